// round 14
// baseline (speedup 1.0000x reference)
#include <cuda_runtime.h>
#include <cuda_fp16.h>
#include <cstdint>

#define NS 512
#define NK 64
#define NVEC 65536
#define M_TILE 128
#define NCTA (NVEC / M_TILE)      /* 512 */
#define NTHR 256

#define OFF_Z      (NVEC*NK)
#define OFF_COMMIT (OFF_Z + NVEC)
#define OFF_CB     (OFF_COMMIT + 1)
#define OFF_ERR    (OFF_CB + 1)

/* smem: A planes persistent; B ring is 2x8KB (single codebook plane). */
#define SM_A    0           /* 2 planes * 128 rows * 128B = 32768, persistent */
#define SM_B    32768       /* 2 stages * 8192 */
#define SM_SCN  49152       /* 512*4 */
#define SM_VN   51200       /* 128*4 */
#define SM_TOT  51712

__device__ float  g_c[NS * NK];      // fp32 codebook
__device__ float  g_cnh[NS];         // 0.5*||c||^2
__device__ __half g_ch0[NS * NK];    // codebook fp16 main plane b0
__device__ int    g_Mi;              // bitcast float: max_s ||c_s - b0_s||
__device__ int    g_nrescan;
__device__ int    g_rescan[NVEC];
__device__ float  g_cpart[64];
__device__ int    g_done2;

__device__ __forceinline__ uint32_t smem_u32(const void* p) {
    uint32_t a;
    asm("{ .reg .u64 t; cvta.to.shared.u64 t, %1; cvt.u32.u64 %0, t; }" : "=r"(a) : "l"(p));
    return a;
}
__device__ __forceinline__ void ldsm_x4(uint32_t* r, uint32_t a) {
    asm volatile("ldmatrix.sync.aligned.m8n8.x4.shared.b16 {%0,%1,%2,%3}, [%4];"
                 : "=r"(r[0]), "=r"(r[1]), "=r"(r[2]), "=r"(r[3]) : "r"(a));
}
__device__ __forceinline__ void mma_f32(float* c, const uint32_t* a, const uint32_t* b) {
    asm volatile("mma.sync.aligned.m16n8k16.row.col.f32.f16.f16.f32 "
                 "{%0,%1,%2,%3}, {%4,%5,%6,%7}, {%8,%9}, {%0,%1,%2,%3};"
                 : "+f"(c[0]), "+f"(c[1]), "+f"(c[2]), "+f"(c[3])
                 : "r"(a[0]), "r"(a[1]), "r"(a[2]), "r"(a[3]), "r"(b[0]), "r"(b[1]));
}
__device__ __forceinline__ void cpa16(uint32_t dst, const void* src) {
    asm volatile("cp.async.cg.shared.global [%0], [%1], 16;" :: "r"(dst), "l"(src));
}
#define CPA_COMMIT() asm volatile("cp.async.commit_group;" ::: "memory")
#define CPA_WAIT(n)  asm volatile("cp.async.wait_group %0;" :: "n"(n) : "memory")

__device__ __forceinline__ void hsplit(float x, __half& h0, __half& h1) {
    h0 = __float2half_rn(x);
    h1 = __float2half_rn(x - __half2float(h0));
}

// ---------------------------------------------------------------------------
// Kernel 1: codebook prep: fp32 + half-norms + fp16 main plane + residual
// norm max (for the trust margin); reset counters.
// ---------------------------------------------------------------------------
__global__ void __launch_bounds__(128) vq_prep_code(const float* __restrict__ c_sum,
                                                    const float* __restrict__ c_count) {
    if (blockIdx.x == 0 && threadIdx.x == 0) { g_nrescan = 0; g_done2 = 0; }
    int warp = (blockIdx.x * blockDim.x + threadIdx.x) >> 5;
    int lane = threadIdx.x & 31;
    if (warp >= NS) return;
    float inv = 1.0f / fmaxf(c_count[warp], 0.01f);
    float a = c_sum[warp * NK + lane] * inv;
    float b = c_sum[warp * NK + 32 + lane] * inv;
    g_c[warp * NK + lane] = a;
    g_c[warp * NK + 32 + lane] = b;
    __half h0 = __float2half_rn(a);
    __half h1 = __float2half_rn(b);
    g_ch0[warp * NK + lane] = h0;
    g_ch0[warp * NK + 32 + lane] = h1;
    float r0 = a - __half2float(h0);
    float r1 = b - __half2float(h1);
    float rr = r0 * r0 + r1 * r1;
    float nh = a * a + b * b;
#pragma unroll
    for (int o = 16; o; o >>= 1) {
        nh += __shfl_xor_sync(0xffffffffu, nh, o);
        rr += __shfl_xor_sync(0xffffffffu, rr, o);
    }
    if (lane == 0) {
        g_cnh[warp] = 0.5f * nh;
        atomicMax(&g_Mi, __float_as_int(sqrtf(rr) * 1.001f));
    }
}

// ---------------------------------------------------------------------------
// Kernel 2: 2-term mma.sync search (16 MMA/npair) + top-2 trust margin.
// A planes stay resident in smem for the exact errs2 dot.
// ---------------------------------------------------------------------------
__global__ void __launch_bounds__(NTHR, 3) vq_mma(const float* __restrict__ vecs,
                                                  float* __restrict__ out) {
    extern __shared__ __align__(128) char smem[];
    uint32_t sb = smem_u32(smem);
    int tid = threadIdx.x;
    int wid = tid >> 5;
    int lane = tid & 31;
    int cta = blockIdx.x;

    for (int i = tid; i < NS; i += NTHR)
        reinterpret_cast<float*>(smem + SM_SCN)[i] = g_cnh[i];

    // fused A conversion: thread pair (2t, 2t+1) owns vector row t (half each)
    {
        int row = tid >> 1;
        int half = tid & 1;
        const float4* src = reinterpret_cast<const float4*>(
            vecs + ((size_t)cta * M_TILE + row) * NK) + half * 8;
        float vn = 0.f;
        int rsw = row & 7;
#pragma unroll
        for (int c = 0; c < 4; c++) {
            int ch = half * 4 + c;
            float4 q0 = src[2 * c], q1 = src[2 * c + 1];
            float x[8] = {q0.x, q0.y, q0.z, q0.w, q1.x, q1.y, q1.z, q1.w};
            union { uint4 u; __half2 h[4]; } p0, p1;
#pragma unroll
            for (int j = 0; j < 4; j++) {
                __half a0, a1, b0, b1;
                hsplit(x[2 * j], a0, a1);
                hsplit(x[2 * j + 1], b0, b1);
                p0.h[j] = __halves2half2(a0, b0);
                p1.h[j] = __halves2half2(a1, b1);
                vn += x[2 * j] * x[2 * j] + x[2 * j + 1] * x[2 * j + 1];
            }
            uint32_t off = row * 128 + ((ch ^ rsw) << 4);
            *reinterpret_cast<uint4*>(smem + SM_A + off) = p0.u;
            *reinterpret_cast<uint4*>(smem + SM_A + 16384 + off) = p1.u;
        }
        vn += __shfl_xor_sync(0xffffffffu, vn, 1);
        if (half == 0) reinterpret_cast<float*>(smem + SM_VN)[row] = vn;
    }
    __syncthreads();

    // register-resident A fragments: [plane][kstep][4] (warp owns 16 rows)
    uint32_t af[2][4][4];
    {
        int r = lane & 15;
        int hi = lane >> 4;
#pragma unroll
        for (int p = 0; p < 2; p++) {
            int row = wid * 16 + r;
#pragma unroll
            for (int k = 0; k < 4; k++) {
                int ch = (2 * k + hi) ^ (row & 7);
                ldsm_x4(af[p][k], sb + SM_A + p * 16384 + row * 128 + ch * 16);
            }
        }
    }
    __syncthreads();

    // B ring: single codebook plane, 8KB per stage
    auto loadB = [&](int tile, int buf) {
#pragma unroll
        for (int j = 0; j < 2; j++) {
            int i = tid + NTHR * j;              // 512 chunks of 16B
            int row = i >> 3, ch = i & 7;
            const __half* src = g_ch0 + ((size_t)tile * 64 + row) * NK + ch * 8;
            cpa16(sb + SM_B + buf * 8192 + row * 128 + (((ch ^ (row & 7))) << 4), src);
        }
    };
    loadB(0, 0);
    CPA_COMMIT();

    const float* scn = reinterpret_cast<const float*>(smem + SM_SCN);
    float best[2] = {-3.4e38f, -3.4e38f};
    float sec[2]  = {-3.4e38f, -3.4e38f};
    int idx[2] = {0, 0};
    int brow_lo = (lane >> 4) << 3;
    int kh = (lane >> 3) & 1;

    for (int tile = 0; tile < 8; tile++) {
        if (tile < 7) { loadB(tile + 1, (tile + 1) & 1); CPA_COMMIT(); CPA_WAIT(1); }
        else CPA_WAIT(0);
        __syncthreads();
        uint32_t bbase = sb + SM_B + (tile & 1) * 8192;

#pragma unroll
        for (int npair = 0; npair < 4; npair++) {
            float acc[2][4] = {};             // [nblock][4], f32 acc, 2 terms
            int row = npair * 16 + brow_lo + (lane & 7);
            int rsw = row & 7;
#pragma unroll
            for (int k = 0; k < 4; k++) {
                uint32_t bf[4];
                ldsm_x4(bf, bbase + row * 128 + (((2 * k + kh) ^ rsw) << 4));
                mma_f32(acc[0], af[0][k], bf + 0);
                mma_f32(acc[1], af[0][k], bf + 2);
                mma_f32(acc[0], af[1][k], bf + 0);
                mma_f32(acc[1], af[1][k], bf + 2);
            }
#pragma unroll
            for (int nb = 0; nb < 2; nb++) {
                int ncol = tile * 64 + npair * 16 + nb * 8 + 2 * (lane & 3);
                float s0 = scn[ncol], s1 = scn[ncol + 1];
                float v;
                v = acc[nb][0] - s0;
                if (v > best[0]) { sec[0] = best[0]; best[0] = v; idx[0] = ncol; }
                else if (v > sec[0]) sec[0] = v;
                v = acc[nb][1] - s1;
                if (v > best[0]) { sec[0] = best[0]; best[0] = v; idx[0] = ncol + 1; }
                else if (v > sec[0]) sec[0] = v;
                v = acc[nb][2] - s0;
                if (v > best[1]) { sec[1] = best[1]; best[1] = v; idx[1] = ncol; }
                else if (v > sec[1]) sec[1] = v;
                v = acc[nb][3] - s1;
                if (v > best[1]) { sec[1] = best[1]; best[1] = v; idx[1] = ncol + 1; }
                else if (v > sec[1]) sec[1] = v;
            }
        }
        __syncthreads();
    }

    // quad reduce with exact top-2 merge (tie -> sec=best forces rescan)
#pragma unroll
    for (int slot = 0; slot < 2; slot++) {
#pragma unroll
        for (int off = 1; off <= 2; off <<= 1) {
            float ob = __shfl_xor_sync(0xffffffffu, best[slot], off);
            int   oi = __shfl_xor_sync(0xffffffffu, idx[slot], off);
            float os = __shfl_xor_sync(0xffffffffu, sec[slot], off);
            if (ob > best[slot]) {
                sec[slot] = fmaxf(best[slot], os);
                best[slot] = ob; idx[slot] = oi;
            } else if (ob == best[slot]) {
                sec[slot] = best[slot];
                if (oi < idx[slot]) idx[slot] = oi;
            } else {
                sec[slot] = fmaxf(sec[slot], ob);
            }
        }
    }

    const float* svn = reinterpret_cast<const float*>(smem + SM_VN);
    float gM = __int_as_float(g_Mi);
#pragma unroll
    for (int slot = 0; slot < 2; slot++) {
        int row = wid * 16 + slot * 8 + (lane >> 2);
        int n = cta * M_TILE + row;
        int ci = idx[slot];
        float vnr = svn[row];
        // exact (~2^-21) dot of chosen code from resident A planes
        float dp = 0.f;
        int q = lane & 3;
        int rsw = row & 7;
#pragma unroll
        for (int j = 0; j < 16; j++) {
            int k = q * 16 + j;
            uint32_t off = row * 128 + ((((k >> 3) ^ rsw)) << 4) + (k & 7) * 2;
            float a0v = __half2float(*reinterpret_cast<const __half*>(smem + SM_A + off));
            float a1v = __half2float(*reinterpret_cast<const __half*>(smem + SM_A + 16384 + off));
            dp += (a0v + a1v) * g_c[ci * NK + k];
        }
        dp += __shfl_xor_sync(0xffffffffu, dp, 1);
        dp += __shfl_xor_sync(0xffffffffu, dp, 2);
        float score = dp - scn[ci];

        const float4* c = reinterpret_cast<const float4*>(g_c + (size_t)ci * NK);
        float4* o = reinterpret_cast<float4*>(out + (size_t)n * NK);
#pragma unroll
        for (int j = lane & 3; j < 16; j += 4) o[j] = c[j];
        if ((lane & 3) == 0) {
            out[OFF_Z + n] = (float)ci;
            out[OFF_ERR + n] = fmaxf(vnr - 2.0f * score, 0.0f);
            float thr = 2.0f * (sqrtf(vnr) * gM + 5e-3f);
            if (best[slot] - sec[slot] <= thr) {
                int pos = atomicAdd(&g_nrescan, 1);
                g_rescan[pos] = n;
            }
        }
    }
}

// ---------------------------------------------------------------------------
// Kernel 3: exact fp32 rescan of ambiguous vectors (one warp per item).
// ---------------------------------------------------------------------------
__global__ void __launch_bounds__(256) vq_rescan(const float* __restrict__ vecs,
                                                 float* __restrict__ out) {
    int gw = (blockIdx.x * 256 + threadIdx.x) >> 5;
    int lane = threadIdx.x & 31;
    int nw = gridDim.x * 8;
    int nitems = g_nrescan;
    for (int it = gw; it < nitems; it += nw) {
        int n = g_rescan[it];
        const float4* vv = reinterpret_cast<const float4*>(vecs + (size_t)n * NK);
        float vr[NK];
        float vn = 0.f;
#pragma unroll
        for (int i = 0; i < 16; i++) {
            float4 q = vv[i];
            vr[4*i] = q.x; vr[4*i+1] = q.y; vr[4*i+2] = q.z; vr[4*i+3] = q.w;
            vn += q.x*q.x + q.y*q.y + q.z*q.z + q.w*q.w;
        }
        float best = -3.4e38f; int bidx = 0;
        for (int j = 0; j < 16; j++) {
            int c = lane * 16 + j;
            const float4* cb = reinterpret_cast<const float4*>(g_c + (size_t)c * NK);
            float d = 0.f;
#pragma unroll
            for (int i = 0; i < 16; i++) {
                float4 q = cb[i];
                d += vr[4*i]*q.x + vr[4*i+1]*q.y + vr[4*i+2]*q.z + vr[4*i+3]*q.w;
            }
            float s = d - g_cnh[c];
            if (s > best) { best = s; bidx = c; }
        }
#pragma unroll
        for (int off = 16; off; off >>= 1) {
            float ob = __shfl_xor_sync(0xffffffffu, best, off);
            int oi = __shfl_xor_sync(0xffffffffu, bidx, off);
            if (ob > best || (ob == best && oi < bidx)) { best = ob; bidx = oi; }
        }
        if (lane == 0) {
            out[OFF_Z + n] = (float)bidx;
            out[OFF_ERR + n] = fmaxf(vn - 2.0f * best, 0.0f);
        }
        if (lane < 16)
            reinterpret_cast<float4*>(out + (size_t)n * NK)[lane] =
                reinterpret_cast<const float4*>(g_c + (size_t)bidx * NK)[lane];
    }
}

// ---------------------------------------------------------------------------
// Kernel 4: l_commit reduce over final errs2 (deterministic fixed trees).
// ---------------------------------------------------------------------------
__global__ void __launch_bounds__(256) vq_commit(float* __restrict__ out) {
    __shared__ float red[256];
    __shared__ int slast;
    int tid = threadIdx.x;
    int base = blockIdx.x * 1024 + tid * 4;
    float e0 = out[OFF_ERR + base + 0];
    float e1 = out[OFF_ERR + base + 1];
    float e2 = out[OFF_ERR + base + 2];
    float e3 = out[OFF_ERR + base + 3];
    red[tid] = (e0 + e1) + (e2 + e3);
    __syncthreads();
#pragma unroll
    for (int off = 128; off > 0; off >>= 1) {
        if (tid < off) red[tid] += red[tid + off];
        __syncthreads();
    }
    if (tid == 0) g_cpart[blockIdx.x] = red[0];
    if (tid == 0) {
        __threadfence();
        slast = (atomicAdd(&g_done2, 1) == 63);
    }
    __syncthreads();
    if (slast) {
        __threadfence();
        if (tid < 64) red[tid] = g_cpart[tid];
        __syncthreads();
#pragma unroll
        for (int off = 32; off > 0; off >>= 1) {
            if (tid < off) red[tid] += red[tid + off];
            __syncthreads();
        }
        if (tid == 0) {
            out[OFF_COMMIT] = red[0] * (1.0f / (float)NVEC);
            out[OFF_CB] = 0.0f;   // l_codebook is identically 0 in forward value
        }
    }
}

extern "C" void kernel_launch(void* const* d_in, const int* in_sizes, int n_in,
                              void* d_out, int out_size) {
    const float* vecs    = (const float*)d_in[0];
    const float* c_sum   = (const float*)d_in[1];
    const float* c_count = (const float*)d_in[2];
    float* out = (float*)d_out;

    cudaFuncSetAttribute(vq_mma, cudaFuncAttributeMaxDynamicSharedMemorySize, SM_TOT);

    vq_prep_code<<<128, 128>>>(c_sum, c_count);
    vq_mma<<<NCTA, NTHR, SM_TOT>>>(vecs, out);
    vq_rescan<<<116, 256>>>(vecs, out);
    vq_commit<<<64, 256>>>(out);
}